// round 9
// baseline (speedup 1.0000x reference)
#include <cuda_runtime.h>
#include <math.h>

// Petrosian fractal features, 5 scales, T=4096, 57 windows/row.
// TWO warps per row (each owns 2048 elems = 8 chunks of 256); 8 warps/CTA =
// 4 rows/CTA; grid 1024. Per chunk: 2 LDG.128/lane (2-chunk prefetch), halo
// via circular shfl, packed dual-segment __reduce_add_sync. Halves join via
// ~1KB smem + one __syncthreads; the 2 indicators straddling elem 2048 are
// fixed up by the first-half warp with one uniform float2 load.
// Windows: zc([128a,128b)) = S[b] - S[a] - bcorr[b].

#define T_LEN 4096
#define N_WIN 57
#define ROWS_PER_CTA 4
#define FULL  0xffffffffu

__global__ __launch_bounds__(256)
void petrosian_kernel(const float* __restrict__ x, float* __restrict__ out) {
    __shared__ int segsm[ROWS_PER_CTA][32];
    __shared__ int bcsm[ROWS_PER_CTA][33];

    const int lane = threadIdx.x & 31;
    const int wid  = threadIdx.x >> 5;
    const int r    = wid >> 1;          // CTA-local row 0..3
    const int h    = wid & 1;           // half 0 / 1
    const int row  = blockIdx.x * ROWS_PER_CTA + r;

    const float* rowp = x + (size_t)row * T_LEN;
    const float4* p4  = (const float4*)(rowp + h * 2048);

    // 2-chunk prefetch (4 LDG.128 in flight)
    float4 b0[2], b1[2];
    #pragma unroll
    for (int i = 0; i < 2; i++) {
        b0[i] = p4[64 * i + lane];
        b1[i] = p4[64 * i + 32 + lane];
    }

    int   segreg = 0, bcreg = 0;     // local lane m (<16): seg sum m / bcorr[m+1]
    int   prevHigh = 0;
    float cx = 0.0f, cd = 0.0f;      // lane 31 carries: x[255], d[254] of prev chunk
    const int nl = (lane + 1) & 31;

    #pragma unroll
    for (int c = 0; c < 8; c++) {
        float4 v0 = b0[c & 1], v1 = b1[c & 1];
        if (c < 6) {
            b0[c & 1] = p4[64 * (c + 2) + lane];
            b1[c & 1] = p4[64 * (c + 2) + 32 + lane];
        }

        float h0x = __shfl_sync(FULL, v0.x, nl);
        float h0y = __shfl_sync(FULL, v0.y, nl);
        float h1x = __shfl_sync(FULL, v1.x, nl);
        float h1y = __shfl_sync(FULL, v1.y, nl);

        // deferred boundary of previous chunk: s[256c-2], s[256c-1] (local)
        if (c > 0) {
            float dA = h0x - cx;       // d[256c-1]
            float dB = h0y - h0x;      // d[256c]
            int te = ((cd * dA < 0.0f) ? 1 : 0) + ((dA * dB < 0.0f) ? 1 : 0);
            te = __shfl_sync(FULL, te, 31);
            if (lane == 2 * c - 1) { segreg = prevHigh + te; bcreg = te; }
        }

        // low half: j = 256c + 4l + {0..3}; lane31 halo = lane0's v1
        float fhx = (lane < 31) ? h0x : h1x;
        float fhy = (lane < 31) ? h0y : h1y;
        float d0 = v0.y - v0.x, d1 = v0.z - v0.y, d2 = v0.w - v0.z;
        float d3 = fhx - v0.w,  d4 = fhy - fhx;
        int sl2 = (d2 * d3 < 0.0f) ? 1 : 0;
        int sl3 = (d3 * d4 < 0.0f) ? 1 : 0;
        int cntLow = ((d0 * d1 < 0.0f) ? 1 : 0) + ((d1 * d2 < 0.0f) ? 1 : 0) + sl2 + sl3;
        int tm = __shfl_sync(FULL, sl2 + sl3, 31);

        // high half: j = 256c + 128 + 4l + {0..3}; lane31: last 2 deferred
        float e0 = v1.y - v1.x, e1 = v1.z - v1.y, e2 = v1.w - v1.z;
        float e3 = h1x - v1.w,  e4 = h1y - h1x;
        int cntHigh = ((e0 * e1 < 0.0f) ? 1 : 0) + ((e1 * e2 < 0.0f) ? 1 : 0);
        if (lane < 31)
            cntHigh += ((e2 * e3 < 0.0f) ? 1 : 0) + ((e3 * e4 < 0.0f) ? 1 : 0);

        int total = __reduce_add_sync(FULL, cntLow | (cntHigh << 16));
        if (lane == 2 * c) { segreg = total & 0xFFFF; bcreg = tm; }
        prevHigh = total >> 16;

        cx = v1.w;   // x[256c+255] (local)
        cd = e2;     // d[256c+254] (local)
    }

    // final local segment (m = 15)
    if (h == 0) {
        // straddling indicators s[2046], s[2047] need x[2048], x[2049]
        float2 nx = *(const float2*)(rowp + 2048);   // uniform address
        float cx31 = __shfl_sync(FULL, cx, 31);
        float cd31 = __shfl_sync(FULL, cd, 31);
        float dA = nx.x - cx31;     // d[2047]
        float dB = nx.y - nx.x;     // d[2048]
        int te = ((cd31 * dA < 0.0f) ? 1 : 0) + ((dA * dB < 0.0f) ? 1 : 0);
        if (lane == 15) { segreg = prevHigh + te; bcreg = te; }
    } else {
        // global end: s[4094], s[4095] invalid
        if (lane == 15) { segreg = prevHigh; bcreg = 0; }
    }

    // publish 16 segment sums + bcorr entries
    if (lane < 16) {
        segsm[r][h * 16 + lane] = segreg;
        bcsm[r][h * 16 + lane + 1] = bcreg;
    }
    __syncthreads();

    // ---- warp w < 4: scan row w's 32 segments, emit 57 outputs ----
    if (wid < ROWS_PER_CTA) {
        const int rr = wid;
        int sc = segsm[rr][lane];
        #pragma unroll
        for (int off = 1; off < 32; off <<= 1) {
            int n = __shfl_up_sync(FULL, sc, off);
            if (lane >= off) sc += n;          // sc = S[lane+1]
        }

        const size_t obase = (size_t)(blockIdx.x * ROWS_PER_CTA + rr) * N_WIN;
        #pragma unroll
        for (int half = 0; half < 2; half++) {
            int k  = lane + half * 32;
            int kk = (k < N_WIN) ? k : 0;
            int w, a; float L;
            if      (kk < 1)  { w = 4096; a = 0;             L = 3.612359948f; }
            else if (kk < 4)  { w = 2048; a = (kk - 1) * 8;  L = 3.311329954f; }
            else if (kk < 11) { w = 1024; a = (kk - 4) * 4;  L = 3.010299957f; }
            else if (kk < 26) { w = 512;  a = (kk - 11) * 2; L = 2.709269961f; }
            else              { w = 256;  a = kk - 26;       L = 2.408239965f; }
            int b = a + (w >> 7);

            int Sb = __shfl_sync(FULL, sc, b - 1);
            int Sa = __shfl_sync(FULL, sc, (a > 0) ? (a - 1) : 0);
            if (a == 0) Sa = 0;

            if (k < N_WIN) {
                float zc = (float)(Sb - Sa - bcsm[rr][b]);
                float wf = (float)w;
                float denom = L + log10f(wf / (wf + 0.4f * zc));
                out[obase + k] = L / denom;
            }
        }
    }
}

extern "C" void kernel_launch(void* const* d_in, const int* in_sizes, int n_in,
                              void* d_out, int out_size) {
    const float* x = (const float*)d_in[0];
    float* out = (float*)d_out;
    int n_rows = in_sizes[0] / T_LEN;                    // 4096
    int n_blocks = n_rows / ROWS_PER_CTA;                // 1024
    petrosian_kernel<<<n_blocks, 256>>>(x, out);
}